// round 2
// baseline (speedup 1.0000x reference)
#include <cuda_runtime.h>

// SpatialTransformer: 3D trilinear warp, smem-tiled gather version.
// vol: [B=2, 160, 192, 160, 1] f32 ; trf: [..., 3] f32 ; out like vol.
//
// Block = 16x16x16 voxel tile. Halo H=4 each side -> 24^3 f32 smem tile
// (border-clamped fill). Gathers hit smem; voxels whose 8 corners fall
// outside the tile (|displacement| > ~4, prob ~6e-5) take an exact global
// fallback path identical to the reference math.

#define DX 160
#define DY 192
#define DZ 160
#define NB 2
#define TS 16           // tile side (voxels)
#define H  4            // halo
#define SD 24           // smem tile side = TS + 2H
#define SELEMS (SD*SD*SD)   // 13824 floats = 54 KB

extern __shared__ float tile[];

__device__ __forceinline__ int iclamp(int v, int hi) {
    return min(max(v, 0), hi);
}

__global__ __launch_bounds__(256, 4)
void warp_tile_kernel(const float* __restrict__ vol,
                      const float* __restrict__ trf,
                      float* __restrict__ out)
{
    const int tid = threadIdx.x;
    const int b  = blockIdx.z / (DX / TS);
    const int x0 = (blockIdx.z % (DX / TS)) * TS;
    const int y0 = blockIdx.y * TS;
    const int z0 = blockIdx.x * TS;

    const float* __restrict__ v = vol + (size_t)b * (DX * DY * DZ);

    // ---------------- cooperative tile load ----------------
    const int gz0 = z0 - H;
    if (z0 >= TS && z0 + TS - 1 + H <= DZ - 1) {
        // interior in z: 24 floats per row = 6 aligned float4 chunks
        // (gz0*4 bytes is 16B-aligned because z0 % 16 == 0)
        for (int idx = tid; idx < SD * SD * 6; idx += 256) {
            int row = idx / 6;
            int c   = idx - row * 6;
            int py  = row % SD;
            int px  = row / SD;
            int gx  = iclamp(x0 - H + px, DX - 1);
            int gy  = iclamp(y0 - H + py, DY - 1);
            const float4* src = reinterpret_cast<const float4*>(
                v + ((size_t)gx * DY + gy) * DZ + gz0);
            float4 val = __ldg(src + c);
            *reinterpret_cast<float4*>(&tile[(px * SD + py) * SD + c * 4]) = val;
        }
    } else {
        // z-border tile: scalar clamped load
        for (int idx = tid; idx < SELEMS; idx += 256) {
            int pz = idx % SD;
            int r  = idx / SD;
            int py = r % SD;
            int px = r / SD;
            int gx = iclamp(x0 - H + px, DX - 1);
            int gy = iclamp(y0 - H + py, DY - 1);
            int gz = iclamp(gz0 + pz, DZ - 1);
            tile[idx] = __ldg(v + ((size_t)gx * DY + gy) * DZ + gz);
        }
    }
    __syncthreads();

    // ---------------- per-voxel warp ----------------
    const int vz = tid & (TS - 1);
    const int vy = tid >> 4;           // 0..15
    const int gy = y0 + vy;
    const int gz = z0 + vz;

    const int xlo = x0 - H, ylo = y0 - H, zlo = z0 - H;
    const int xhi = xlo + SD - 1, yhi = ylo + SD - 1, zhi = zlo + SD - 1;

    size_t idx0 = (((size_t)b * DX + x0) * DY + gy) * DZ + gz;

    for (int vx = 0; vx < TS; ++vx) {
        const int gx = x0 + vx;
        const size_t idx = idx0 + (size_t)vx * (DY * DZ);

        const float tx = __ldg(trf + idx * 3 + 0);
        const float ty = __ldg(trf + idx * 3 + 1);
        const float tz = __ldg(trf + idx * 3 + 2);

        float lx = fminf(fmaxf((float)gx + tx, 0.0f), (float)(DX - 1));
        float ly = fminf(fmaxf((float)gy + ty, 0.0f), (float)(DY - 1));
        float lz = fminf(fmaxf((float)gz + tz, 0.0f), (float)(DZ - 1));

        int ix0 = (int)floorf(lx);
        int iy0 = (int)floorf(ly);
        int iz0 = (int)floorf(lz);
        int ix1 = min(ix0 + 1, DX - 1);
        int iy1 = min(iy0 + 1, DY - 1);
        int iz1 = min(iz0 + 1, DZ - 1);

        float wx1 = (float)ix1 - lx;   // lower-corner weight (d1)
        float wy1 = (float)iy1 - ly;
        float wz1 = (float)iz1 - lz;
        float wx0 = 1.0f - wx1;
        float wy0 = 1.0f - wy1;
        float wz0 = 1.0f - wz1;

        float v000, v001, v010, v011, v100, v101, v110, v111;

        bool in_tile = (ix0 >= xlo) & (ix1 <= xhi) &
                       (iy0 >= ylo) & (iy1 <= yhi) &
                       (iz0 >= zlo) & (iz1 <= zhi);

        if (in_tile) {
            int sx0 = ix0 - xlo, sx1 = ix1 - xlo;
            int sy0 = iy0 - ylo, sy1 = iy1 - ylo;
            int sz0 = iz0 - zlo, sz1 = iz1 - zlo;
            const float* t00 = &tile[(sx0 * SD + sy0) * SD];
            const float* t01 = &tile[(sx0 * SD + sy1) * SD];
            const float* t10 = &tile[(sx1 * SD + sy0) * SD];
            const float* t11 = &tile[(sx1 * SD + sy1) * SD];
            v000 = t00[sz0]; v001 = t00[sz1];
            v010 = t01[sz0]; v011 = t01[sz1];
            v100 = t10[sz0]; v101 = t10[sz1];
            v110 = t11[sz0]; v111 = t11[sz1];
        } else {
            // rare fallback: exact global gather
            const float* p00 = v + ((size_t)ix0 * DY + iy0) * DZ;
            const float* p01 = v + ((size_t)ix0 * DY + iy1) * DZ;
            const float* p10 = v + ((size_t)ix1 * DY + iy0) * DZ;
            const float* p11 = v + ((size_t)ix1 * DY + iy1) * DZ;
            v000 = __ldg(p00 + iz0); v001 = __ldg(p00 + iz1);
            v010 = __ldg(p01 + iz0); v011 = __ldg(p01 + iz1);
            v100 = __ldg(p10 + iz0); v101 = __ldg(p10 + iz1);
            v110 = __ldg(p11 + iz0); v111 = __ldg(p11 + iz1);
        }

        float c00 = v000 * wz1 + v001 * wz0;
        float c01 = v010 * wz1 + v011 * wz0;
        float c10 = v100 * wz1 + v101 * wz0;
        float c11 = v110 * wz1 + v111 * wz0;

        float c0 = c00 * wy1 + c01 * wy0;
        float c1 = c10 * wy1 + c11 * wy0;

        out[idx] = c0 * wx1 + c1 * wx0;
    }
}

extern "C" void kernel_launch(void* const* d_in, const int* in_sizes, int n_in,
                              void* d_out, int out_size)
{
    const float* vol = (const float*)d_in[0];
    const float* trf = (const float*)d_in[1];
    float* out = (float*)d_out;

    cudaFuncSetAttribute(warp_tile_kernel,
                         cudaFuncAttributeMaxDynamicSharedMemorySize,
                         SELEMS * (int)sizeof(float));

    dim3 grid(DZ / TS, DY / TS, NB * (DX / TS));  // (10, 12, 20)
    warp_tile_kernel<<<grid, 256, SELEMS * sizeof(float)>>>(vol, trf, out);
}

// round 3
// speedup vs baseline: 1.2848x; 1.2848x over previous
#include <cuda_runtime.h>

// SpatialTransformer: 3D trilinear warp, smem-tiled, ILP-4 version.
// vol: [B=2, 160, 192, 160, 1] f32 ; trf: [..., 3] f32 ; out like vol.
//
// Block = 16x16x16 output tile. Smem tile = 22(x) x 22(y) x 24(z) floats
// (halo 3 in x/y; z covers [z0-4, z0+19], float4-aligned), padded row
// stride 25 for conflict-free LDS. Each thread handles 4 consecutive z
// voxels (float4 trf load + float4 out store), 4 x-quads in a short loop.
// Corners outside the tile (~0.5% of voxels) take an exact global fallback.

#define DX 160
#define DY 192
#define DZ 160
#define NB 2
#define TS 16
#define SX 22          // tile extent in x
#define SY 22          // tile extent in y
#define SZ 24          // tile extent in z (values [z0-4 .. z0+19])
#define SZP 25         // padded z row stride (bank spread)
#define SELEMS (SX*SY*SZP)   // 12100 floats = 48400 B

extern __shared__ float tile[];

__device__ __forceinline__ int iclamp(int v, int hi) {
    return min(max(v, 0), hi);
}

__global__ __launch_bounds__(256, 4)
void warp_tile2_kernel(const float* __restrict__ vol,
                       const float* __restrict__ trf,
                       float* __restrict__ out)
{
    const int tid = threadIdx.x;
    const int b  = blockIdx.z / (DX / TS);
    const int x0 = (blockIdx.z % (DX / TS)) * TS;
    const int y0 = blockIdx.y * TS;
    const int z0 = blockIdx.x * TS;

    const float* __restrict__ v = vol + (size_t)b * (DX * DY * DZ);
    const int xlo = x0 - 3, ylo = y0 - 3, zlo = z0 - 4;

    // ---------------- cooperative tile load ----------------
    if (zlo >= 0 && z0 + 19 <= DZ - 1) {
        // z-interior: 24 z values = 6 aligned float4 per (x,y) row
        // ((z0-4)*4 bytes is 16B-aligned since z0 % 16 == 0)
        for (int idx = tid; idx < SX * SY * 6; idx += 256) {
            int c   = idx % 6;
            int row = idx / 6;
            int py  = row % SY;
            int px  = row / SY;
            int gx  = iclamp(xlo + px, DX - 1);
            int gy  = iclamp(ylo + py, DY - 1);
            float4 val = __ldg(reinterpret_cast<const float4*>(
                                   v + ((size_t)gx * DY + gy) * DZ + zlo) + c);
            float* dst = &tile[(px * SY + py) * SZP + c * 4];
            dst[0] = val.x; dst[1] = val.y; dst[2] = val.z; dst[3] = val.w;
        }
    } else {
        // z-border: scalar clamped load
        for (int idx = tid; idx < SX * SY * SZ; idx += 256) {
            int pz = idx % SZ;
            int r  = idx / SZ;
            int py = r % SY;
            int px = r / SY;
            int gx = iclamp(xlo + px, DX - 1);
            int gy = iclamp(ylo + py, DY - 1);
            int gz = iclamp(zlo + pz, DZ - 1);
            tile[(px * SY + py) * SZP + pz] =
                __ldg(v + ((size_t)gx * DY + gy) * DZ + gz);
        }
    }
    __syncthreads();

    // ---------------- per-voxel warp, 4 z-voxels per thread ----------------
    const int zg = tid & 3;            // z quad within tile (0..3)
    const int vy = (tid >> 2) & 15;    // 0..15
    const int xs = tid >> 6;           // 0..3
    const int gy = y0 + vy;
    const int zb = z0 + zg * 4;

    const float4* __restrict__ trf4 = reinterpret_cast<const float4*>(trf);
    float4* __restrict__ out4 = reinterpret_cast<float4*>(out);

#pragma unroll 1
    for (int it = 0; it < 4; ++it) {
        const int gx = x0 + it * 4 + xs;
        const size_t g = (((size_t)b * DX + gx) * DY + gy) * (DZ / 4)
                         + (z0 >> 2) + zg;

        float4 t0 = __ldg(&trf4[g * 3 + 0]);
        float4 t1 = __ldg(&trf4[g * 3 + 1]);
        float4 t2 = __ldg(&trf4[g * 3 + 2]);

        float tx[4] = {t0.x, t0.w, t1.z, t2.y};
        float ty[4] = {t0.y, t1.x, t1.w, t2.z};
        float tz[4] = {t0.z, t1.y, t2.x, t2.w};

        float4 res;
        float* rp = reinterpret_cast<float*>(&res);

#pragma unroll
        for (int j = 0; j < 4; ++j) {
            float lx = fminf(fmaxf((float)gx + tx[j],       0.0f), (float)(DX - 1));
            float ly = fminf(fmaxf((float)gy + ty[j],       0.0f), (float)(DY - 1));
            float lz = fminf(fmaxf((float)(zb + j) + tz[j], 0.0f), (float)(DZ - 1));

            int ix0 = (int)floorf(lx);
            int iy0 = (int)floorf(ly);
            int iz0 = (int)floorf(lz);
            int ix1 = min(ix0 + 1, DX - 1);
            int iy1 = min(iy0 + 1, DY - 1);
            int iz1 = min(iz0 + 1, DZ - 1);

            float wx1 = (float)ix1 - lx;    // lower-corner weight (d1)
            float wy1 = (float)iy1 - ly;
            float wz1 = (float)iz1 - lz;
            float wx0 = 1.0f - wx1;
            float wy0 = 1.0f - wy1;
            float wz0 = 1.0f - wz1;

            float v000, v001, v010, v011, v100, v101, v110, v111;

            unsigned sux = (unsigned)(ix0 - xlo);
            unsigned suy = (unsigned)(iy0 - ylo);
            unsigned suz = (unsigned)(iz0 - zlo);

            if (sux <= (unsigned)(SX - 2) &&
                suy <= (unsigned)(SY - 2) &&
                suz <= (unsigned)(SZ - 2)) {
                int sy_step = (iy1 - iy0) * SZP;   // 0 or 25
                int sx_step = (ix1 - ix0) * (SY * SZP);
                int sz_step = iz1 - iz0;           // 0 or 1
                const float* t00 = &tile[((int)sux * SY + (int)suy) * SZP + (int)suz];
                const float* t01 = t00 + sy_step;
                const float* t10 = t00 + sx_step;
                const float* t11 = t10 + sy_step;
                v000 = t00[0]; v001 = t00[sz_step];
                v010 = t01[0]; v011 = t01[sz_step];
                v100 = t10[0]; v101 = t10[sz_step];
                v110 = t11[0]; v111 = t11[sz_step];
            } else {
                // rare exact global fallback
                const float* p00 = v + ((size_t)ix0 * DY + iy0) * DZ;
                const float* p01 = v + ((size_t)ix0 * DY + iy1) * DZ;
                const float* p10 = v + ((size_t)ix1 * DY + iy0) * DZ;
                const float* p11 = v + ((size_t)ix1 * DY + iy1) * DZ;
                v000 = __ldg(p00 + iz0); v001 = __ldg(p00 + iz1);
                v010 = __ldg(p01 + iz0); v011 = __ldg(p01 + iz1);
                v100 = __ldg(p10 + iz0); v101 = __ldg(p10 + iz1);
                v110 = __ldg(p11 + iz0); v111 = __ldg(p11 + iz1);
            }

            float c00 = v000 * wz1 + v001 * wz0;
            float c01 = v010 * wz1 + v011 * wz0;
            float c10 = v100 * wz1 + v101 * wz0;
            float c11 = v110 * wz1 + v111 * wz0;

            float c0 = c00 * wy1 + c01 * wy0;
            float c1 = c10 * wy1 + c11 * wy0;

            rp[j] = c0 * wx1 + c1 * wx0;
        }

        out4[g] = res;
    }
}

extern "C" void kernel_launch(void* const* d_in, const int* in_sizes, int n_in,
                              void* d_out, int out_size)
{
    const float* vol = (const float*)d_in[0];
    const float* trf = (const float*)d_in[1];
    float* out = (float*)d_out;

    cudaFuncSetAttribute(warp_tile2_kernel,
                         cudaFuncAttributeMaxDynamicSharedMemorySize,
                         SELEMS * (int)sizeof(float));

    dim3 grid(DZ / TS, DY / TS, NB * (DX / TS));  // (10, 12, 20)
    warp_tile2_kernel<<<grid, 256, SELEMS * sizeof(float)>>>(vol, trf, out);
}